// round 16
// baseline (speedup 1.0000x reference)
#include <cuda_runtime.h>
#include <cuda_bf16.h>
#include <math.h>

// Fixed problem shapes
#define T_STEPS 512
#define BATCH   32
#define DIM     1024
#define BD      (BATCH*DIM)          // 32768
#define NCTA    128                  // 32 e-groups x 4 b-groups
#define NTHR    1024                 // 32 warps
#define E_CTA   32
#define B_CTA   8
#define NEG     32
#define WSTR    1032                 // bf16 elems per smem W_h row (2064B: conflict-free)

// Device scratch (allocation-free rule)
__device__ float              g_wx [(size_t)T_STEPS*BD];
__device__ __nv_bfloat16      g_hbf[(size_t)(T_STEPS+1)*BD];
__device__ unsigned long long g_tag[2][BATCH][NEG];   // { ss bits, step tag }
// bf16 hi/lo decompositions for the HMMA input GEMM
__device__ __nv_bfloat16      g_xhi[(size_t)T_STEPS*BD];   // X: [16384][1024]
__device__ __nv_bfloat16      g_xlo[(size_t)T_STEPS*BD];
__device__ __nv_bfloat16      g_whi[DIM*DIM];
__device__ __nv_bfloat16      g_wlo[DIM*DIM];

// ---------------------------------------------------------------------------
// helpers
// ---------------------------------------------------------------------------
__device__ __forceinline__ __nv_bfloat162 u2b(unsigned u) {
    return *reinterpret_cast<__nv_bfloat162*>(&u);
}
__device__ __forceinline__ void dot8(__nv_bfloat162& a, uint4 h, uint4 wv) {
    a = __hfma2(u2b(h.x), u2b(wv.x), a);
    a = __hfma2(u2b(h.y), u2b(wv.y), a);
    a = __hfma2(u2b(h.z), u2b(wv.z), a);
    a = __hfma2(u2b(h.w), u2b(wv.w), a);
}
__device__ __forceinline__ void cpasync16(void* dst, const void* src) {
    unsigned ds = (unsigned)__cvta_generic_to_shared(dst);
    asm volatile("cp.async.ca.shared.global [%0], [%1], 16;" :: "r"(ds), "l"(src));
}
#define CP_COMMIT() asm volatile("cp.async.commit_group;")
#define CP_WAIT0()  asm volatile("cp.async.wait_group 0;" ::: "memory")

__device__ __forceinline__ void tag_pub(unsigned long long* slot, float ss, unsigned tag) {
    unsigned long long v = ((unsigned long long)tag << 32) | (unsigned long long)__float_as_uint(ss);
    asm volatile("st.release.gpu.global.u64 [%0], %1;" :: "l"(slot), "l"(v) : "memory");
}
__device__ __forceinline__ float tag_spin(const unsigned long long* slot, unsigned want) {
    unsigned long long v;
    unsigned done;
    do {
        asm volatile("ld.acquire.gpu.global.u64 %0, [%1];" : "=l"(v) : "l"(slot) : "memory");
        done = ((unsigned)(v >> 32) == want);
    } while (!__all_sync(0xffffffffu, done));
    return __uint_as_float((unsigned)v);
}

// m16n8k16 bf16 MMA (baseline PTX, maps to HMMA on the tensor pipe)
#define MMA(c, a, b) \
    asm volatile("mma.sync.aligned.m16n8k16.row.col.f32.bf16.bf16.f32 " \
        "{%0,%1,%2,%3}, {%4,%5,%6,%7}, {%8,%9}, {%0,%1,%2,%3};" \
        : "+f"((c)[0]), "+f"((c)[1]), "+f"((c)[2]), "+f"((c)[3]) \
        : "r"((a)[0]), "r"((a)[1]), "r"((a)[2]), "r"((a)[3]), \
          "r"((b)[0]), "r"((b)[1]))

// ---------------------------------------------------------------------------
// Kernel A: fp32 -> bf16 hi/lo decomposition (one float4 per thread).
// Block 0 of the X pass also clears g_tag for this replay.
// ---------------------------------------------------------------------------
__global__ void __launch_bounds__(256)
convert_hilo(const float* __restrict__ src, __nv_bfloat16* __restrict__ hi,
             __nv_bfloat16* __restrict__ lo, int n4, int clear_tags)
{
    if (clear_tags && blockIdx.x == 0) {
        unsigned long long* tp = &g_tag[0][0][0];
        for (int i = threadIdx.x; i < 2*BATCH*NEG; i += 256) tp[i] = 0ull;
    }
    int i = blockIdx.x*256 + threadIdx.x;
    if (i >= n4) return;
    float4 v = ((const float4*)src)[i];
    __nv_bfloat16 h0 = __float2bfloat16_rn(v.x);
    __nv_bfloat16 h1 = __float2bfloat16_rn(v.y);
    __nv_bfloat16 h2 = __float2bfloat16_rn(v.z);
    __nv_bfloat16 h3 = __float2bfloat16_rn(v.w);
    __nv_bfloat162 hh0 = __halves2bfloat162(h0, h1);
    __nv_bfloat162 hh1 = __halves2bfloat162(h2, h3);
    __nv_bfloat162 ll0 = __floats2bfloat162_rn(v.x - __bfloat162float(h0),
                                               v.y - __bfloat162float(h1));
    __nv_bfloat162 ll1 = __floats2bfloat162_rn(v.z - __bfloat162float(h2),
                                               v.w - __bfloat162float(h3));
    ((uint2*)hi)[i] = make_uint2(*(unsigned*)&hh0, *(unsigned*)&hh1);
    ((uint2*)lo)[i] = make_uint2(*(unsigned*)&ll0, *(unsigned*)&ll1);
}

// ---------------------------------------------------------------------------
// Kernel B: HMMA GEMM  g_wx[m][e] = alpha*( X[m,:].W[e,:] + bias[e] )
// bf16 hi/lo 3-pass (Ahi.Bhi + Ahi.Blo + Alo.Bhi), fp32 accum.
// CTA: 128 thr (4 warps, 2m x 2n), tile 64m x 128e; warp = 32m x 64e =
// 2 m16-tiles x 8 n8-tiles. Fragments loaded straight from global per the
// canonical m16n8k16 mapping (g = lane>>2, q = lane&3):
//   A row-major: a0 (row g,   k 2q..2q+1)  a1 (row g+8, same)
//                a2 (row g,   k 2q+8..+9)  a3 (row g+8, same)
//   B col-major: b0 (n g, k 2q..2q+1)      b1 (n g, k 2q+8..+9)
//   C: c0 (row g, e 2q) c1 (e 2q+1) c2/c3 (row g+8)
// ---------------------------------------------------------------------------
__global__ void __launch_bounds__(128)
mma_gemm(const float* __restrict__ bias, const float* __restrict__ log_alpha)
{
    const int tid  = threadIdx.x;
    const int wid  = tid >> 5;
    const int lane = tid & 31;
    const int g    = lane >> 2;
    const int q    = lane & 3;
    const int wm   = wid & 1;
    const int wn   = wid >> 1;
    const int m0   = blockIdx.y*64  + wm*32;
    const int e0   = blockIdx.x*128 + wn*64;

    float acc[2][8][4];
    #pragma unroll
    for (int mt = 0; mt < 2; mt++)
        #pragma unroll
        for (int nt = 0; nt < 8; nt++)
            #pragma unroll
            for (int j = 0; j < 4; j++) acc[mt][nt][j] = 0.f;

    #pragma unroll 1
    for (int k0 = 0; k0 < DIM; k0 += 16) {
        unsigned ah[2][4], al[2][4], bh[8][2], bl[8][2];
        #pragma unroll
        for (int mt = 0; mt < 2; mt++) {
            size_t r = (size_t)(m0 + mt*16 + g)*DIM + k0 + 2*q;
            ah[mt][0] = *(const unsigned*)&g_xhi[r];
            ah[mt][1] = *(const unsigned*)&g_xhi[r + 8*DIM];
            ah[mt][2] = *(const unsigned*)&g_xhi[r + 8];
            ah[mt][3] = *(const unsigned*)&g_xhi[r + 8*DIM + 8];
            al[mt][0] = *(const unsigned*)&g_xlo[r];
            al[mt][1] = *(const unsigned*)&g_xlo[r + 8*DIM];
            al[mt][2] = *(const unsigned*)&g_xlo[r + 8];
            al[mt][3] = *(const unsigned*)&g_xlo[r + 8*DIM + 8];
        }
        #pragma unroll
        for (int nt = 0; nt < 8; nt++) {
            size_t r = (size_t)(e0 + nt*8 + g)*DIM + k0 + 2*q;
            bh[nt][0] = *(const unsigned*)&g_whi[r];
            bh[nt][1] = *(const unsigned*)&g_whi[r + 8];
            bl[nt][0] = *(const unsigned*)&g_wlo[r];
            bl[nt][1] = *(const unsigned*)&g_wlo[r + 8];
        }
        #pragma unroll
        for (int mt = 0; mt < 2; mt++)
            #pragma unroll
            for (int nt = 0; nt < 8; nt++) {
                MMA(acc[mt][nt], ah[mt], bh[nt]);
                MMA(acc[mt][nt], ah[mt], bl[nt]);
                MMA(acc[mt][nt], al[mt], bh[nt]);
            }
    }

    const float alpha = expf(log_alpha[0]);
    #pragma unroll
    for (int mt = 0; mt < 2; mt++) {
        int m = m0 + mt*16 + g;
        #pragma unroll
        for (int nt = 0; nt < 8; nt++) {
            int e = e0 + nt*8 + 2*q;
            float b0v = bias[e], b1v = bias[e + 1];
            float2 s0, s1;
            s0.x = alpha*(acc[mt][nt][0] + b0v);
            s0.y = alpha*(acc[mt][nt][1] + b1v);
            s1.x = alpha*(acc[mt][nt][2] + b0v);
            s1.y = alpha*(acc[mt][nt][3] + b1v);
            *(float2*)&g_wx[(size_t)m*DIM + e]       = s0;
            *(float2*)&g_wx[(size_t)(m + 8)*DIM + e] = s1;
        }
    }
}

// ---------------------------------------------------------------------------
// Kernel C: persistent recurrence (R12, proven). Fused tag sync:
//   slot[t&1][b][eg] = { ss(pre[t]), tag = t+1 } via st.release; owner-warp
//   acquire-spin on the 32 tags is the inter-CTA barrier.
// CTA (eg = bid&31, bg = bid>>5): e in [eg*32,+32), b in [bg*8,+8).
// ---------------------------------------------------------------------------
#define SW_BYTES   (E_CTA*WSTR*2)                 // 66048
#define SRED_OFF   SW_BYTES                       // 16KB: [ks 16][b_l 8][e 32] fp32
#define SH_OFF     (SRED_OFF + 16*B_CTA*E_CTA*4)  // 16KB: [b 8][dim 1024] bf16
#define SMEM_BYTES (SH_OFF + B_CTA*DIM*2)         // 98432

__global__ void __launch_bounds__(NTHR, 1)
recur(const float* __restrict__ h0, const float* __restrict__ W_h,
      const float* __restrict__ log_beta, float* __restrict__ out)
{
    extern __shared__ char smraw[];
    __nv_bfloat16* s_w   = (__nv_bfloat16*)smraw;
    float*         s_red = (float*)(smraw + SRED_OFF);
    __nv_bfloat16* s_h   = (__nv_bfloat16*)(smraw + SH_OFF);

    float* outs = out;
    float* hout = out + (size_t)T_STEPS*BD;

    const int tid  = threadIdx.x;
    const int w    = tid >> 5;
    const int lane = tid & 31;
    const int eg   = blockIdx.x & 31;
    const int bg   = blockIdx.x >> 5;
    const int e0   = eg * E_CTA;
    const int b0   = bg * B_CTA;
    const int bg2  = w & 1;
    const int ks   = w >> 1;

    const float beta = 0.1f / (1.0f + expf(-log_beta[0]));

    for (int i = tid; i < E_CTA*(DIM/4); i += NTHR) {
        int r = i >> 8, q = i & 255;
        float4 v = *(const float4*)&W_h[(size_t)(e0 + r)*DIM + q*4];
        __nv_bfloat162 p0 = __floats2bfloat162_rn(v.x, v.y);
        __nv_bfloat162 p1 = __floats2bfloat162_rn(v.z, v.w);
        *(__nv_bfloat162*)&s_w[r*WSTR + q*4]     = p0;
        *(__nv_bfloat162*)&s_w[r*WSTR + q*4 + 2] = p1;
    }
    if (tid < 64) {
        int idx = eg*64 + tid;
        const float4* src = (const float4*)h0 + (size_t)b0*(DIM/4);
        float4 v = src[idx];
        size_t o4 = (size_t)b0*(DIM/4) + idx;
        ((float4*)hout)[o4] = v;
        __nv_bfloat162 p0 = __floats2bfloat162_rn(v.x, v.y);
        __nv_bfloat162 p1 = __floats2bfloat162_rn(v.z, v.w);
        *(__nv_bfloat162*)&g_hbf[o4*4]     = p0;
        *(__nv_bfloat162*)&g_hbf[o4*4 + 2] = p1;
    }
    float pre_self = 0.f;
    if (w < 8) pre_self = h0[(size_t)(b0 + w)*DIM + e0 + lane];
    float wxv_next = 0.f;
    if (w < 8) wxv_next = __ldg(&g_wx[(size_t)(b0 + w)*DIM + e0 + lane]);

    __syncthreads();

    if (tid < B_CTA)
        tag_pub(&g_tag[0][b0 + tid][eg], (float)E_CTA * (1.0f - 1e-6f), 1u);

    for (int t = 0; t < T_STEPS; t++) {
        const float wxv = wxv_next;

        float rv = 0.f;
        if (w < 8) {
            float p = tag_spin(&g_tag[t & 1][b0 + w][lane], (unsigned)(t + 1));
            p += __shfl_xor_sync(0xffffffffu, p, 16);
            p += __shfl_xor_sync(0xffffffffu, p, 8);
            p += __shfl_xor_sync(0xffffffffu, p, 4);
            p += __shfl_xor_sync(0xffffffffu, p, 2);
            p += __shfl_xor_sync(0xffffffffu, p, 1);
            rv = rsqrtf(p * (1.0f/DIM) + 1e-6f);
        }
        __syncthreads();

        cpasync16(s_h + tid*8,
                  g_hbf + (size_t)t*BD + (size_t)b0*DIM + tid*8);
        CP_COMMIT();
        CP_WAIT0();
        __syncthreads();

        const uint4* wrow = (const uint4*)((const char*)s_w + lane*(WSTR*2) + ks*128);
        const __nv_bfloat16* hrow = s_h + (size_t)(bg2*4)*DIM + ks*64;
        __nv_bfloat162 a0 = u2b(0u), a1 = u2b(0u), a2 = u2b(0u), a3 = u2b(0u);
        #pragma unroll
        for (int c = 0; c < 8; c++) {
            uint4 wv  = wrow[c];
            uint4 h0v = *(const uint4*)(hrow + 0*DIM + c*8);
            uint4 h1v = *(const uint4*)(hrow + 1*DIM + c*8);
            uint4 h2v = *(const uint4*)(hrow + 2*DIM + c*8);
            uint4 h3v = *(const uint4*)(hrow + 3*DIM + c*8);
            dot8(a0, h0v, wv);
            dot8(a1, h1v, wv);
            dot8(a2, h2v, wv);
            dot8(a3, h3v, wv);
        }
        {
            float2 f0 = __bfloat1622float2(a0);
            float2 f1 = __bfloat1622float2(a1);
            float2 f2 = __bfloat1622float2(a2);
            float2 f3 = __bfloat1622float2(a3);
            int base = ks*256 + bg2*128 + lane;
            s_red[base]      = f0.x + f0.y;
            s_red[base + 32] = f1.x + f1.y;
            s_red[base + 64] = f2.x + f2.y;
            s_red[base + 96] = f3.x + f3.y;
        }
        if (w < 8 && t + 1 < T_STEPS)
            wxv_next = __ldg(&g_wx[(size_t)(t+1)*BD + (size_t)(b0 + w)*DIM + e0 + lane]);
        __syncthreads();

        if (w < 8) {
            float dot = 0.f;
            #pragma unroll
            for (int k = 0; k < 16; k++)
                dot += s_red[k*256 + w*32 + lane];

            float hn = rv * pre_self;
            float pre_new = hn + wxv + beta * rv * dot;
            size_t o = (size_t)t*BD + (size_t)(b0 + w)*DIM + e0 + lane;
            g_hbf[o + BD] = __float2bfloat16(pre_new);

            float ss = pre_new * pre_new;
            ss += __shfl_xor_sync(0xffffffffu, ss, 16);
            ss += __shfl_xor_sync(0xffffffffu, ss, 8);
            ss += __shfl_xor_sync(0xffffffffu, ss, 4);
            ss += __shfl_xor_sync(0xffffffffu, ss, 2);
            ss += __shfl_xor_sync(0xffffffffu, ss, 1);
            __syncwarp();
            if (lane == 0)
                tag_pub(&g_tag[(t + 1) & 1][b0 + w][eg], ss, (unsigned)(t + 2));
            pre_self = pre_new;

            hout[o] = hn;
            if (t > 0) {
                float sg = 1.0f / (1.0f + __expf(-hn));
                outs[o - BD] = hn*hn*sg;
            }
        }
    }

    if (w < 8) {
        float p = tag_spin(&g_tag[T_STEPS & 1][b0 + w][lane], (unsigned)(T_STEPS + 1));
        p += __shfl_xor_sync(0xffffffffu, p, 16);
        p += __shfl_xor_sync(0xffffffffu, p, 8);
        p += __shfl_xor_sync(0xffffffffu, p, 4);
        p += __shfl_xor_sync(0xffffffffu, p, 2);
        p += __shfl_xor_sync(0xffffffffu, p, 1);
        float rv = rsqrtf(p * (1.0f/DIM) + 1e-6f);
        float hn = rv * pre_self;
        size_t o = (size_t)(b0 + w)*DIM + e0 + lane;
        hout[(size_t)T_STEPS*BD + o] = hn;
        float sg = 1.0f / (1.0f + __expf(-hn));
        outs[(size_t)(T_STEPS-1)*BD + o] = hn*hn*sg;
    }
}

// ---------------------------------------------------------------------------
// Single stream, bare launches only (proven capturable):
//   convert(X, +tag clear) -> convert(W) -> mma_gemm -> recur
// ---------------------------------------------------------------------------
extern "C" void kernel_launch(void* const* d_in, const int* in_sizes, int n_in,
                              void* d_out, int out_size) {
    const float* x    = (const float*)d_in[0];
    const float* h0   = (const float*)d_in[1];
    const float* W    = (const float*)d_in[2];
    const float* W_h  = (const float*)d_in[3];
    const float* bias = (const float*)d_in[4];
    const float* la   = (const float*)d_in[5];
    const float* lb   = (const float*)d_in[6];
    float* out = (float*)d_out;

    static int configured = 0;
    if (!configured) {
        cudaFuncSetAttribute(recur, cudaFuncAttributeMaxDynamicSharedMemorySize,
                             SMEM_BYTES);
        configured = 1;
    }

    __nv_bfloat16 *xhi, *xlo, *whi, *wlo;
    cudaGetSymbolAddress((void**)&xhi, g_xhi);
    cudaGetSymbolAddress((void**)&xlo, g_xlo);
    cudaGetSymbolAddress((void**)&whi, g_whi);
    cudaGetSymbolAddress((void**)&wlo, g_wlo);

    convert_hilo<<<16384, 256>>>(x, xhi, xlo, (T_STEPS*BD)/4, 1);
    convert_hilo<<<1024, 256>>>(W, whi, wlo, (DIM*DIM)/4, 0);
    mma_gemm<<<dim3(8, 256), 128>>>(bias, la);
    recur<<<NCTA, NTHR, SMEM_BYTES>>>(h0, W_h, lb, out);
}

// round 17
// speedup vs baseline: 1.1831x; 1.1831x over previous
#include <cuda_runtime.h>
#include <cuda_bf16.h>
#include <math.h>

// Fixed problem shapes
#define T_STEPS 512
#define BATCH   32
#define DIM     1024
#define BD      (BATCH*DIM)          // 32768
#define NCTA    128                  // 32 e-groups x 4 b-groups
#define NTHR    1024                 // 32 warps
#define E_CTA   32
#define B_CTA   8
#define NEG     32
#define WSTR    1032                 // bf16 elems per smem W_h row (2064B: conflict-free)

// Device scratch (allocation-free rule)
__device__ float              g_wx [(size_t)T_STEPS*BD];
__device__ __nv_bfloat16      g_hbf[(size_t)(T_STEPS+1)*BD];
__device__ unsigned long long g_tag[2][BATCH][NEG];   // { ss bits, step tag }
// bf16 hi/lo decompositions for the HMMA input GEMM
__device__ __nv_bfloat16      g_xhi[(size_t)T_STEPS*BD];   // X: [16384][1024]
__device__ __nv_bfloat16      g_xlo[(size_t)T_STEPS*BD];
__device__ __nv_bfloat16      g_whi[DIM*DIM];
__device__ __nv_bfloat16      g_wlo[DIM*DIM];

// ---------------------------------------------------------------------------
// helpers
// ---------------------------------------------------------------------------
__device__ __forceinline__ __nv_bfloat162 u2b(unsigned u) {
    return *reinterpret_cast<__nv_bfloat162*>(&u);
}
__device__ __forceinline__ void dot8(__nv_bfloat162& a, uint4 h, uint4 wv) {
    a = __hfma2(u2b(h.x), u2b(wv.x), a);
    a = __hfma2(u2b(h.y), u2b(wv.y), a);
    a = __hfma2(u2b(h.z), u2b(wv.z), a);
    a = __hfma2(u2b(h.w), u2b(wv.w), a);
}
__device__ __forceinline__ void cpasync16(void* dst, const void* src) {
    unsigned ds = (unsigned)__cvta_generic_to_shared(dst);
    asm volatile("cp.async.ca.shared.global [%0], [%1], 16;" :: "r"(ds), "l"(src));
}
#define CP_COMMIT() asm volatile("cp.async.commit_group;")
#define CP_WAIT0()  asm volatile("cp.async.wait_group 0;" ::: "memory")

__device__ __forceinline__ void tag_pub(unsigned long long* slot, float ss, unsigned tag) {
    unsigned long long v = ((unsigned long long)tag << 32) | (unsigned long long)__float_as_uint(ss);
    asm volatile("st.release.gpu.global.u64 [%0], %1;" :: "l"(slot), "l"(v) : "memory");
}
__device__ __forceinline__ float tag_spin(const unsigned long long* slot, unsigned want) {
    unsigned long long v;
    unsigned done;
    do {
        asm volatile("ld.acquire.gpu.global.u64 %0, [%1];" : "=l"(v) : "l"(slot) : "memory");
        done = ((unsigned)(v >> 32) == want);
    } while (!__all_sync(0xffffffffu, done));
    return __uint_as_float((unsigned)v);
}

// m16n8k16 bf16 MMA (baseline PTX -> HMMA)
#define MMA(c, a, b) \
    asm volatile("mma.sync.aligned.m16n8k16.row.col.f32.bf16.bf16.f32 " \
        "{%0,%1,%2,%3}, {%4,%5,%6,%7}, {%8,%9}, {%0,%1,%2,%3};" \
        : "+f"((c)[0]), "+f"((c)[1]), "+f"((c)[2]), "+f"((c)[3]) \
        : "r"((a)[0]), "r"((a)[1]), "r"((a)[2]), "r"((a)[3]), \
          "r"((b)[0]), "r"((b)[1]))

__device__ __forceinline__ void lm_x4(unsigned* r, unsigned addr) {
    asm volatile("ldmatrix.sync.aligned.m8n8.x4.shared.b16 {%0,%1,%2,%3}, [%4];"
        : "=r"(r[0]), "=r"(r[1]), "=r"(r[2]), "=r"(r[3]) : "r"(addr));
}

// ---------------------------------------------------------------------------
// Kernel A: fp32 -> bf16 hi/lo decomposition (one float4 per thread).
// Block 0 of the X pass also clears g_tag for this replay.
// ---------------------------------------------------------------------------
__global__ void __launch_bounds__(256)
convert_hilo(const float* __restrict__ src, __nv_bfloat16* __restrict__ hi,
             __nv_bfloat16* __restrict__ lo, int n4, int clear_tags)
{
    if (clear_tags && blockIdx.x == 0) {
        unsigned long long* tp = &g_tag[0][0][0];
        for (int i = threadIdx.x; i < 2*BATCH*NEG; i += 256) tp[i] = 0ull;
    }
    int i = blockIdx.x*256 + threadIdx.x;
    if (i >= n4) return;
    float4 v = ((const float4*)src)[i];
    __nv_bfloat16 h0 = __float2bfloat16_rn(v.x);
    __nv_bfloat16 h1 = __float2bfloat16_rn(v.y);
    __nv_bfloat16 h2 = __float2bfloat16_rn(v.z);
    __nv_bfloat16 h3 = __float2bfloat16_rn(v.w);
    __nv_bfloat162 hh0 = __halves2bfloat162(h0, h1);
    __nv_bfloat162 hh1 = __halves2bfloat162(h2, h3);
    __nv_bfloat162 ll0 = __floats2bfloat162_rn(v.x - __bfloat162float(h0),
                                               v.y - __bfloat162float(h1));
    __nv_bfloat162 ll1 = __floats2bfloat162_rn(v.z - __bfloat162float(h2),
                                               v.w - __bfloat162float(h3));
    ((uint2*)hi)[i] = make_uint2(*(unsigned*)&hh0, *(unsigned*)&hh1);
    ((uint2*)lo)[i] = make_uint2(*(unsigned*)&ll0, *(unsigned*)&ll1);
}

// ---------------------------------------------------------------------------
// Kernel B: HMMA GEMM via smem + ldmatrix.
//   g_wx[m][e] = alpha*( X[m,:].W[e,:] + bias[e] ),  bf16 hi/lo 3-pass.
// CTA 256 thr (8 warps: 4 wm x 2 wn), tile 128m x 128e, K panels of 32.
// smem rows: 32 bf16 = 64B = 4 chunks of 16B, swizzle chunk ^= (row>>1)&3.
// Warp tile 32m x 64e: per panel 24 ldmatrix.x4 feed 96 MMAs.
// Grid (et 8, mt 128), et-fastest: X tiles shared via L2 by the 8 et-CTAs.
// ---------------------------------------------------------------------------
__global__ void __launch_bounds__(256)
mma_gemm(const float* __restrict__ bias, const float* __restrict__ log_alpha)
{
    __shared__ __align__(128) char sAhi[128*64];
    __shared__ __align__(128) char sAlo[128*64];
    __shared__ __align__(128) char sBhi[128*64];
    __shared__ __align__(128) char sBlo[128*64];

    const int tid  = threadIdx.x;
    const int wid  = tid >> 5;
    const int lane = tid & 31;
    const int wm   = wid & 3;         // 0..3: 32m each
    const int wn   = wid >> 2;        // 0..1: 64e each
    const int m0c  = blockIdx.y * 128;
    const int e0c  = blockIdx.x * 128;
    const int tile = lane >> 3;       // ldmatrix tile id 0..3
    const int tr   = lane & 7;        // row within tile

    // staging descriptors: 8 chunks of 16B per thread per panel
    const __nv_bfloat16* gsrc[8];
    unsigned sdst[8];
    #pragma unroll
    for (int it = 0; it < 8; it++) {
        int idx = it*256 + tid;           // 0..2047
        int arr = idx >> 9;               // 0:Ahi 1:Alo 2:Bhi 3:Blo
        int row = (idx >> 2) & 127;
        int c   = idx & 3;
        int cs  = c ^ ((row >> 1) & 3);
        const __nv_bfloat16* g =
            (arr == 0) ? g_xhi + (size_t)(m0c + row)*DIM :
            (arr == 1) ? g_xlo + (size_t)(m0c + row)*DIM :
            (arr == 2) ? g_whi + (size_t)(e0c + row)*DIM :
                         g_wlo + (size_t)(e0c + row)*DIM;
        gsrc[it] = g + c*8;
        char* sb = (arr == 0) ? sAhi : (arr == 1) ? sAlo : (arr == 2) ? sBhi : sBlo;
        sdst[it] = (unsigned)__cvta_generic_to_shared(sb + row*64 + cs*16);
    }

    float acc[2][8][4];
    #pragma unroll
    for (int mt = 0; mt < 2; mt++)
        #pragma unroll
        for (int nt = 0; nt < 8; nt++)
            #pragma unroll
            for (int j = 0; j < 4; j++) acc[mt][nt][j] = 0.f;

    const unsigned sA_hi = (unsigned)__cvta_generic_to_shared(sAhi);
    const unsigned sA_lo = (unsigned)__cvta_generic_to_shared(sAlo);
    const unsigned sB_hi = (unsigned)__cvta_generic_to_shared(sBhi);
    const unsigned sB_lo = (unsigned)__cvta_generic_to_shared(sBlo);

    for (int kp = 0; kp < 32; kp++) {
        // ---- stage panel (k columns kp*32 .. +32) ----
        #pragma unroll
        for (int it = 0; it < 8; it++) {
            unsigned ds = sdst[it];
            asm volatile("cp.async.ca.shared.global [%0], [%1], 16;"
                         :: "r"(ds), "l"(gsrc[it] + kp*32));
        }
        CP_COMMIT();
        CP_WAIT0();
        __syncthreads();

        #pragma unroll
        for (int s = 0; s < 2; s++) {
            // A fragments: tile order m-lo/m-hi x k-lo/k-hi
            unsigned ah[2][4], al[2][4];
            #pragma unroll
            for (int mt = 0; mt < 2; mt++) {
                int row = wm*32 + mt*16 + (tile & 1)*8 + tr;
                int ch  = (2*s + (tile >> 1)) ^ ((row >> 1) & 3);
                unsigned off = (unsigned)(row*64 + ch*16);
                lm_x4(ah[mt], sA_hi + off);
                lm_x4(al[mt], sA_lo + off);
            }
            // B fragments: x4 = {n_j k-lo, n_j k-hi, n_j+1 k-lo, n_j+1 k-hi}
            #pragma unroll
            for (int jp = 0; jp < 4; jp++) {
                int row = wn*64 + jp*16 + (tile >> 1)*8 + tr;
                int ch  = (2*s + (tile & 1)) ^ ((row >> 1) & 3);
                unsigned off = (unsigned)(row*64 + ch*16);
                unsigned bh[4], bl[4];
                lm_x4(bh, sB_hi + off);
                lm_x4(bl, sB_lo + off);
                #pragma unroll
                for (int mt = 0; mt < 2; mt++)
                    #pragma unroll
                    for (int j = 0; j < 2; j++) {
                        int nt = jp*2 + j;
                        MMA(acc[mt][nt], ah[mt], &bh[2*j]);
                        MMA(acc[mt][nt], ah[mt], &bl[2*j]);
                        MMA(acc[mt][nt], al[mt], &bh[2*j]);
                    }
            }
        }
        __syncthreads();   // all ldmatrix reads done before next stage
    }

    // ---- epilogue ----
    const float alpha = expf(log_alpha[0]);
    const int g = lane >> 2;
    const int q = lane & 3;
    #pragma unroll
    for (int mt = 0; mt < 2; mt++) {
        int m = m0c + wm*32 + mt*16 + g;
        #pragma unroll
        for (int nt = 0; nt < 8; nt++) {
            int e = e0c + wn*64 + nt*8 + 2*q;
            float b0v = bias[e], b1v = bias[e + 1];
            float2 s0, s1;
            s0.x = alpha*(acc[mt][nt][0] + b0v);
            s0.y = alpha*(acc[mt][nt][1] + b1v);
            s1.x = alpha*(acc[mt][nt][2] + b0v);
            s1.y = alpha*(acc[mt][nt][3] + b1v);
            *(float2*)&g_wx[(size_t)m*DIM + e]       = s0;
            *(float2*)&g_wx[(size_t)(m + 8)*DIM + e] = s1;
        }
    }
}

// ---------------------------------------------------------------------------
// Kernel C: persistent recurrence (proven R12/R16). Fused tag sync.
// CTA (eg = bid&31, bg = bid>>5): e in [eg*32,+32), b in [bg*8,+8).
// ---------------------------------------------------------------------------
#define SW_BYTES   (E_CTA*WSTR*2)                 // 66048
#define SRED_OFF   SW_BYTES                       // 16KB: [ks 16][b_l 8][e 32] fp32
#define SH_OFF     (SRED_OFF + 16*B_CTA*E_CTA*4)  // 16KB: [b 8][dim 1024] bf16
#define SMEM_BYTES (SH_OFF + B_CTA*DIM*2)         // 98432

__global__ void __launch_bounds__(NTHR, 1)
recur(const float* __restrict__ h0, const float* __restrict__ W_h,
      const float* __restrict__ log_beta, float* __restrict__ out)
{
    extern __shared__ char smraw[];
    __nv_bfloat16* s_w   = (__nv_bfloat16*)smraw;
    float*         s_red = (float*)(smraw + SRED_OFF);
    __nv_bfloat16* s_h   = (__nv_bfloat16*)(smraw + SH_OFF);

    float* outs = out;
    float* hout = out + (size_t)T_STEPS*BD;

    const int tid  = threadIdx.x;
    const int w    = tid >> 5;
    const int lane = tid & 31;
    const int eg   = blockIdx.x & 31;
    const int bg   = blockIdx.x >> 5;
    const int e0   = eg * E_CTA;
    const int b0   = bg * B_CTA;
    const int bg2  = w & 1;
    const int ks   = w >> 1;

    const float beta = 0.1f / (1.0f + expf(-log_beta[0]));

    for (int i = tid; i < E_CTA*(DIM/4); i += NTHR) {
        int r = i >> 8, q = i & 255;
        float4 v = *(const float4*)&W_h[(size_t)(e0 + r)*DIM + q*4];
        __nv_bfloat162 p0 = __floats2bfloat162_rn(v.x, v.y);
        __nv_bfloat162 p1 = __floats2bfloat162_rn(v.z, v.w);
        *(__nv_bfloat162*)&s_w[r*WSTR + q*4]     = p0;
        *(__nv_bfloat162*)&s_w[r*WSTR + q*4 + 2] = p1;
    }
    if (tid < 64) {
        int idx = eg*64 + tid;
        const float4* src = (const float4*)h0 + (size_t)b0*(DIM/4);
        float4 v = src[idx];
        size_t o4 = (size_t)b0*(DIM/4) + idx;
        ((float4*)hout)[o4] = v;
        __nv_bfloat162 p0 = __floats2bfloat162_rn(v.x, v.y);
        __nv_bfloat162 p1 = __floats2bfloat162_rn(v.z, v.w);
        *(__nv_bfloat162*)&g_hbf[o4*4]     = p0;
        *(__nv_bfloat162*)&g_hbf[o4*4 + 2] = p1;
    }
    float pre_self = 0.f;
    if (w < 8) pre_self = h0[(size_t)(b0 + w)*DIM + e0 + lane];
    float wxv_next = 0.f;
    if (w < 8) wxv_next = __ldg(&g_wx[(size_t)(b0 + w)*DIM + e0 + lane]);

    __syncthreads();

    if (tid < B_CTA)
        tag_pub(&g_tag[0][b0 + tid][eg], (float)E_CTA * (1.0f - 1e-6f), 1u);

    for (int t = 0; t < T_STEPS; t++) {
        const float wxv = wxv_next;

        float rv = 0.f;
        if (w < 8) {
            float p = tag_spin(&g_tag[t & 1][b0 + w][lane], (unsigned)(t + 1));
            p += __shfl_xor_sync(0xffffffffu, p, 16);
            p += __shfl_xor_sync(0xffffffffu, p, 8);
            p += __shfl_xor_sync(0xffffffffu, p, 4);
            p += __shfl_xor_sync(0xffffffffu, p, 2);
            p += __shfl_xor_sync(0xffffffffu, p, 1);
            rv = rsqrtf(p * (1.0f/DIM) + 1e-6f);
        }
        __syncthreads();

        cpasync16(s_h + tid*8,
                  g_hbf + (size_t)t*BD + (size_t)b0*DIM + tid*8);
        CP_COMMIT();
        CP_WAIT0();
        __syncthreads();

        const uint4* wrow = (const uint4*)((const char*)s_w + lane*(WSTR*2) + ks*128);
        const __nv_bfloat16* hrow = s_h + (size_t)(bg2*4)*DIM + ks*64;
        __nv_bfloat162 a0 = u2b(0u), a1 = u2b(0u), a2 = u2b(0u), a3 = u2b(0u);
        #pragma unroll
        for (int c = 0; c < 8; c++) {
            uint4 wv  = wrow[c];
            uint4 h0v = *(const uint4*)(hrow + 0*DIM + c*8);
            uint4 h1v = *(const uint4*)(hrow + 1*DIM + c*8);
            uint4 h2v = *(const uint4*)(hrow + 2*DIM + c*8);
            uint4 h3v = *(const uint4*)(hrow + 3*DIM + c*8);
            dot8(a0, h0v, wv);
            dot8(a1, h1v, wv);
            dot8(a2, h2v, wv);
            dot8(a3, h3v, wv);
        }
        {
            float2 f0 = __bfloat1622float2(a0);
            float2 f1 = __bfloat1622float2(a1);
            float2 f2 = __bfloat1622float2(a2);
            float2 f3 = __bfloat1622float2(a3);
            int base = ks*256 + bg2*128 + lane;
            s_red[base]      = f0.x + f0.y;
            s_red[base + 32] = f1.x + f1.y;
            s_red[base + 64] = f2.x + f2.y;
            s_red[base + 96] = f3.x + f3.y;
        }
        if (w < 8 && t + 1 < T_STEPS)
            wxv_next = __ldg(&g_wx[(size_t)(t+1)*BD + (size_t)(b0 + w)*DIM + e0 + lane]);
        __syncthreads();

        if (w < 8) {
            float dot = 0.f;
            #pragma unroll
            for (int k = 0; k < 16; k++)
                dot += s_red[k*256 + w*32 + lane];

            float hn = rv * pre_self;
            float pre_new = hn + wxv + beta * rv * dot;
            size_t o = (size_t)t*BD + (size_t)(b0 + w)*DIM + e0 + lane;
            g_hbf[o + BD] = __float2bfloat16(pre_new);

            float ss = pre_new * pre_new;
            ss += __shfl_xor_sync(0xffffffffu, ss, 16);
            ss += __shfl_xor_sync(0xffffffffu, ss, 8);
            ss += __shfl_xor_sync(0xffffffffu, ss, 4);
            ss += __shfl_xor_sync(0xffffffffu, ss, 2);
            ss += __shfl_xor_sync(0xffffffffu, ss, 1);
            __syncwarp();
            if (lane == 0)
                tag_pub(&g_tag[(t + 1) & 1][b0 + w][eg], ss, (unsigned)(t + 2));
            pre_self = pre_new;

            hout[o] = hn;
            if (t > 0) {
                float sg = 1.0f / (1.0f + __expf(-hn));
                outs[o - BD] = hn*hn*sg;
            }
        }
    }

    if (w < 8) {
        float p = tag_spin(&g_tag[T_STEPS & 1][b0 + w][lane], (unsigned)(T_STEPS + 1));
        p += __shfl_xor_sync(0xffffffffu, p, 16);
        p += __shfl_xor_sync(0xffffffffu, p, 8);
        p += __shfl_xor_sync(0xffffffffu, p, 4);
        p += __shfl_xor_sync(0xffffffffu, p, 2);
        p += __shfl_xor_sync(0xffffffffu, p, 1);
        float rv = rsqrtf(p * (1.0f/DIM) + 1e-6f);
        float hn = rv * pre_self;
        size_t o = (size_t)(b0 + w)*DIM + e0 + lane;
        hout[(size_t)T_STEPS*BD + o] = hn;
        float sg = 1.0f / (1.0f + __expf(-hn));
        outs[(size_t)(T_STEPS-1)*BD + o] = hn*hn*sg;
    }
}

// ---------------------------------------------------------------------------
// Single stream, bare launches (proven capturable):
//   convert(X, +tag clear) -> convert(W) -> mma_gemm -> recur
// ---------------------------------------------------------------------------
extern "C" void kernel_launch(void* const* d_in, const int* in_sizes, int n_in,
                              void* d_out, int out_size) {
    const float* x    = (const float*)d_in[0];
    const float* h0   = (const float*)d_in[1];
    const float* W    = (const float*)d_in[2];
    const float* W_h  = (const float*)d_in[3];
    const float* bias = (const float*)d_in[4];
    const float* la   = (const float*)d_in[5];
    const float* lb   = (const float*)d_in[6];
    float* out = (float*)d_out;

    static int configured = 0;
    if (!configured) {
        cudaFuncSetAttribute(recur, cudaFuncAttributeMaxDynamicSharedMemorySize,
                             SMEM_BYTES);
        configured = 1;
    }

    __nv_bfloat16 *xhi, *xlo, *whi, *wlo;
    cudaGetSymbolAddress((void**)&xhi, g_xhi);
    cudaGetSymbolAddress((void**)&xlo, g_xlo);
    cudaGetSymbolAddress((void**)&whi, g_whi);
    cudaGetSymbolAddress((void**)&wlo, g_wlo);

    convert_hilo<<<16384, 256>>>(x, xhi, xlo, (T_STEPS*BD)/4, 1);
    convert_hilo<<<1024, 256>>>(W, whi, wlo, (DIM*DIM)/4, 0);
    mma_gemm<<<dim3(8, 128), 256>>>(bias, la);   // et-fastest: X L2 reuse
    recur<<<NCTA, NTHR, SMEM_BYTES>>>(h0, W_h, lb, out);
}